// round 15
// baseline (speedup 1.0000x reference)
#include <cuda_runtime.h>
#include <cuda_fp16.h>
#include <cstdint>

// BrainSphereCNN on GB300. Round 15: R14 base. New: intra-ks LDSM/MMA
// interleave in gemm_mma (load ahi/bh -> pass1 -> load alo/bl -> pass2/3)
// to spread crossbar bursts under the MMA shadow; cp.async spread 3/3/2/0;
// faster stats_final. Numerics unchanged (middle: fp16 hi/lo 3-term,
// final: plain fp16), rel_err ~2.8e-4.

#define NN    40962
#define C     128
#define NB0   641
#define NBM   321
#define NCLS  36
#define EPSBN 1e-5f
#define NLAY  14
#define LOSCALE 2048.0f
#define INV_LOSCALE (1.0f / 2048.0f)

// ---------------- device scratch ----------------
__device__ float   g_Y[(size_t)NN * C];
__device__ __half  g_Xhi[(size_t)NN * C];
__device__ __half  g_Xlo[(size_t)NN * C];
__device__ __half  g_Whi[(size_t)NLAY * C * 896];  // W^T hi [l][n][k]
__device__ __half  g_Wlo[(size_t)NLAY * C * 896];  // W^T lo * 2048
__device__ __half  g_Wlf[64 * 896];                // final W^T fp16, N padded
__device__ float   g_psum[NB0 * C];
__device__ float   g_psq [NB0 * C];
__device__ float   g_scale[C];
__device__ float   g_shift[C];
__device__ int     g_ticket[NLAY];

// ---------------- PTX helpers ----------------
__device__ __forceinline__ uint32_t smem_u32(const void* p) {
    uint32_t a;
    asm("{ .reg .u64 t; cvta.to.shared.u64 t, %1; cvt.u32.u64 %0, t; }" : "=r"(a) : "l"(p));
    return a;
}

#define LDSM_X4(r0, r1, r2, r3, addr) \
    asm volatile("ldmatrix.sync.aligned.m8n8.x4.shared.b16 {%0,%1,%2,%3}, [%4];" \
                 : "=r"(r0), "=r"(r1), "=r"(r2), "=r"(r3) : "r"(addr))

#define MMA_F32(d0, d1, d2, d3, a0, a1, a2, a3, b0, b1) \
    asm volatile("mma.sync.aligned.m16n8k16.row.col.f32.f16.f16.f32 " \
                 "{%0,%1,%2,%3}, {%4,%5,%6,%7}, {%8,%9}, {%0,%1,%2,%3};" \
                 : "+f"(d0), "+f"(d1), "+f"(d2), "+f"(d3) \
                 : "r"(a0), "r"(a1), "r"(a2), "r"(a3), "r"(b0), "r"(b1))

#define MMA_F16(c0, c1, a0, a1, a2, a3, b0, b1) \
    asm volatile("mma.sync.aligned.m16n8k16.row.col.f16.f16.f16.f16 " \
                 "{%0,%1}, {%2,%3,%4,%5}, {%6,%7}, {%0,%1};" \
                 : "+r"(c0), "+r"(c1) \
                 : "r"(a0), "r"(a1), "r"(a2), "r"(a3), "r"(b0), "r"(b1))

#define CP16(dst, src) \
    asm volatile("cp.async.cg.shared.global [%0], [%1], 16;" :: "r"(dst), "l"(src) : "memory")
#define CP_COMMIT() asm volatile("cp.async.commit_group;" ::: "memory")
#define CP_WAIT(n)  asm volatile("cp.async.wait_group %0;" :: "n"(n) : "memory")

// ---------------- weight prep (middle layers) ----------------
__global__ void prep_w(const float* __restrict__ Wm) {
    __shared__ float tile[32][33];
    const int l = blockIdx.z, k0 = blockIdx.x * 32, n0 = blockIdx.y * 32;
    const int tx = threadIdx.x, ty = threadIdx.y;
    tile[ty][tx] = Wm[((size_t)l * 896 + k0 + ty) * 128 + n0 + tx];
    __syncthreads();
    float w = tile[tx][ty];
    __half hi = __float2half_rn(w);
    __half lo = __float2half_rn((w - __half2float(hi)) * LOSCALE);
    size_t o = ((size_t)l * 128 + n0 + ty) * 896 + (k0 + tx);
    g_Whi[o] = hi;
    g_Wlo[o] = lo;
}

// ---------------- weight prep (final layer) ----------------
__global__ void prep_wl(const float* __restrict__ Wl) {
    int o = blockIdx.x * 256 + threadIdx.x;
    if (o >= 64 * 896) return;
    int n = o / 896, k = o - n * 896;
    float v = (n < NCLS) ? Wl[(size_t)k * NCLS + n] : 0.f;
    g_Wlf[o] = __float2half_rn(v);
}

// ---------------- layer 0 ----------------
__global__ __launch_bounds__(128) void layer0_kernel(
    const float* __restrict__ x, const int* __restrict__ idx,
    const float* __restrict__ W0, const float* __restrict__ b0)
{
    __shared__ float sA[64 * 21];
    const int t = threadIdx.x;
    const int m0 = blockIdx.x * 64;
    for (int e = t; e < 64 * 21; e += 128) {
        int r = e / 21, k = e - r * 21;
        int m = m0 + r;
        float v = 0.f;
        if (m < NN) {
            int j = k / 3, c = k - j * 3;
            v = x[idx[m * 7 + j] * 3 + c];
        }
        sA[e] = v;
    }
    __syncthreads();
    float w[21];
#pragma unroll
    for (int k = 0; k < 21; k++) w[k] = W0[k * C + t];
    const float bias = b0[t];
    float s = 0.f, sq = 0.f;
    int rows = NN - m0; if (rows > 64) rows = 64;
    for (int r = 0; r < rows; r++) {
        float acc = bias;
#pragma unroll
        for (int k = 0; k < 21; k++) acc = fmaf(sA[r * 21 + k], w[k], acc);
        g_Y[(size_t)(m0 + r) * C + t] = acc;
        s += acc; sq += acc * acc;
    }
    g_psum[blockIdx.x * C + t] = s;
    g_psq [blockIdx.x * C + t] = sq;
}

// ---------------- BN stats finalize (layer 0 only), float4 x 32-slice --------
__global__ __launch_bounds__(1024) void stats_final(int nblk, const float* __restrict__ g,
                                                    const float* __restrict__ be)
{
    __shared__ float sS[32][128], sQ[32][128];
    const int t  = threadIdx.x;
    const int cg = t & 31;           // channel group (4 channels)
    const int sl = t >> 5;           // 0..31 slices
    float4 s = make_float4(0.f, 0.f, 0.f, 0.f);
    float4 q = make_float4(0.f, 0.f, 0.f, 0.f);
    for (int b = sl; b < nblk; b += 32) {
        float4 ps = *(const float4*)&g_psum[b * C + cg * 4];
        float4 pq = *(const float4*)&g_psq [b * C + cg * 4];
        s.x += ps.x; s.y += ps.y; s.z += ps.z; s.w += ps.w;
        q.x += pq.x; q.y += pq.y; q.z += pq.z; q.w += pq.w;
    }
    *(float4*)&sS[sl][cg * 4] = s;
    *(float4*)&sQ[sl][cg * 4] = q;
    __syncthreads();
    if (t < 128) {
        float S = 0.f, Q = 0.f;
#pragma unroll
        for (int u = 0; u < 32; u++) { S += sS[u][t]; Q += sQ[u][t]; }
        const float inv_n = 1.f / (float)NN;
        float mu  = S * inv_n;
        float var = Q * inv_n - mu * mu;
        float sc  = g[t] * rsqrtf(var + EPSBN);
        g_scale[t] = sc;
        g_shift[t] = be[t] - mu * sc;
    }
}

// ---------------- convert: Y -> fp16 hi + scaled lo (8 channels/thread) ------
__global__ __launch_bounds__(512) void convert_kernel() {
    int e = blockIdx.x * 512 + threadIdx.x;
    if (e >= NN * 16) return;
    const int c0 = (e & 15) * 8;
    const float4* src = (const float4*)g_Y + e * 2;
    float4 ya = src[0], yb = src[1];
    float p[8] = { ya.x, ya.y, ya.z, ya.w, yb.x, yb.y, yb.z, yb.w };
    uint32_t hw[4], lw[4];
#pragma unroll
    for (int i = 0; i < 4; i++) {
        float h0 = fmaxf(fmaf(p[2*i],   g_scale[c0 + 2*i],   g_shift[c0 + 2*i]),   0.f);
        float h1 = fmaxf(fmaf(p[2*i+1], g_scale[c0 + 2*i+1], g_shift[c0 + 2*i+1]), 0.f);
        __half a0 = __float2half_rn(h0), a1 = __float2half_rn(h1);
        __half l0 = __float2half_rn((h0 - __half2float(a0)) * LOSCALE);
        __half l1 = __float2half_rn((h1 - __half2float(a1)) * LOSCALE);
        hw[i] = (uint32_t)__half_as_ushort(a0) | ((uint32_t)__half_as_ushort(a1) << 16);
        lw[i] = (uint32_t)__half_as_ushort(l0) | ((uint32_t)__half_as_ushort(l1) << 16);
    }
    ((uint4*)g_Xhi)[e] = make_uint4(hw[0], hw[1], hw[2], hw[3]);
    ((uint4*)g_Xlo)[e] = make_uint4(lw[0], lw[1], lw[2], lw[3]);
}

// ---------------- middle layer GEMM ----------------
#define PITCH   72
#define BUFB    18432
#define STAGEB  (4 * BUFB)               // 73728
#define SM_REDS STAGEB
#define SM_REDQ (SM_REDS + 2048)
#define SM_IDX  (2 * STAGEB)             // 147456 : 896 ints
#define SM_BIAS (SM_IDX + 3584)
#define GEMM_SMEM (SM_BIAS + 512)        // 151552
#define STAGE_PITCH 132

__global__ void __launch_bounds__(512, 1)
gemm_mma(int layer, const int* __restrict__ idx,
         const float* __restrict__ bias,
         const float* __restrict__ gamma, const float* __restrict__ beta)
{
    extern __shared__ char smp[];
    const uint32_t sb = smem_u32(smp);
    const int t    = threadIdx.x;
    const int lane = t & 31;
    const int wid  = t >> 5;
    const int wm   = wid >> 2;
    const int wn   = wid & 3;
    const int m0   = blockIdx.x * 128;

    const __half* __restrict__ Whi = g_Whi + (size_t)layer * C * 896;
    const __half* __restrict__ Wlo = g_Wlo + (size_t)layer * C * 896;

    int* sIdx = (int*)(smp + SM_IDX);
    float* sBias = (float*)(smp + SM_BIAS);
    for (int e = t; e < 896; e += 512) {
        int row = e / 7, j = e - row * 7;
        int m = m0 + row;
        sIdx[e] = (m < NN) ? idx[m * 7 + j] : 0;
    }
    if (t < 128) sBias[t] = bias[t];
    __syncthreads();

    const int grow = t >> 2;
    const int gq   = t & 3;
    const uint32_t dstOff = (uint32_t)grow * (PITCH * 2) + (uint32_t)gq * 32;
    const __half* wHrow = Whi + (size_t)grow * 896;
    const __half* wLrow = Wlo + (size_t)grow * 896;

    auto issueAll = [&](int c, int s) {
        const int j = c >> 1, h = c & 1;
        const int nb = sIdx[grow * 7 + j];
        const char* aH = (const char*)(g_Xhi + (size_t)nb * C + h * 64) + gq * 32;
        const char* aL = (const char*)(g_Xlo + (size_t)nb * C + h * 64) + gq * 32;
        const char* wH = (const char*)(wHrow + c * 64) + gq * 32;
        const char* wL = (const char*)(wLrow + c * 64) + gq * 32;
        uint32_t base = sb + s * STAGEB + dstOff;
        CP16(base,                 aH);
        CP16(base + 16,            aH + 16);
        CP16(base + BUFB,          aL);
        CP16(base + BUFB + 16,     aL + 16);
        CP16(base + 2 * BUFB,      wH);
        CP16(base + 2 * BUFB + 16, wH + 16);
        CP16(base + 3 * BUFB,      wL);
        CP16(base + 3 * BUFB + 16, wL + 16);
        CP_COMMIT();
    };

    float    d[2][4][4];
    uint32_t c16[2][4][2];
#pragma unroll
    for (int mt = 0; mt < 2; mt++)
#pragma unroll
        for (int nt = 0; nt < 4; nt++) {
#pragma unroll
            for (int i = 0; i < 4; i++) d[mt][nt][i] = 0.f;
            c16[mt][nt][0] = 0u; c16[mt][nt][1] = 0u;
        }

    const int a_row  = wm * 32 + (lane & 15);
    const int a_koff = (lane >> 4) * 8;
    const int b_n    = wn * 32 + (lane & 7) + ((lane >> 4) & 1) * 8;
    const int b_koff = ((lane >> 3) & 1) * 8;
    const int kph    = wid & 3;

    issueAll(0, 0);
    CP_WAIT(0);
    __syncthreads();

    for (int c = 0; c < 14; c++) {
        const int s = c & 1;
        const uint32_t sAh = sb + s * STAGEB;
        const uint32_t sAl = sAh + BUFB;
        const uint32_t sBh = sAh + 2 * BUFB;
        const uint32_t sBl = sAh + 3 * BUFB;

        const bool pf = (c + 1 < 14);
        const char *paH = nullptr, *paL = nullptr, *pwH = nullptr, *pwL = nullptr;
        uint32_t nbase = 0;
        if (pf) {
            const int cn = c + 1, j = cn >> 1, h = cn & 1;
            const int nb = sIdx[grow * 7 + j];
            paH = (const char*)(g_Xhi + (size_t)nb * C + h * 64) + gq * 32;
            paL = (const char*)(g_Xlo + (size_t)nb * C + h * 64) + gq * 32;
            pwH = (const char*)(wHrow + cn * 64) + gq * 32;
            pwL = (const char*)(wLrow + cn * 64) + gq * 32;
            nbase = sb + (s ^ 1) * STAGEB + dstOff;
        }

#pragma unroll
        for (int ks = 0; ks < 4; ks++) {
            const int kk = (ks + kph) & 3;
            // --- group 1: ahi + bh only ---
            uint32_t ahi[2][4];
#pragma unroll
            for (int mt = 0; mt < 2; mt++) {
                uint32_t ra = sAh + ((a_row + mt * 16) * PITCH + kk * 16 + a_koff) * 2;
                LDSM_X4(ahi[mt][0], ahi[mt][1], ahi[mt][2], ahi[mt][3], ra);
            }
            uint32_t bh[4][2];
#pragma unroll
            for (int p = 0; p < 2; p++) {
                uint32_t rb = sBh + ((b_n + p * 16) * PITCH + kk * 16 + b_koff) * 2;
                uint32_t r0, r1, r2, r3;
                LDSM_X4(r0, r1, r2, r3, rb);
                bh[2 * p][0] = r0; bh[2 * p][1] = r1;
                bh[2 * p + 1][0] = r2; bh[2 * p + 1][1] = r3;
            }
            // spread next-chunk cp.async: 3/3/2/0 across ks
            if (pf) {
                if (ks == 0) { CP16(nbase,            paH); CP16(nbase + 16,        paH + 16);
                               CP16(nbase + BUFB,     paL); }
                if (ks == 1) { CP16(nbase + BUFB + 16, paL + 16);
                               CP16(nbase + 2 * BUFB,  pwH); CP16(nbase + 2 * BUFB + 16, pwH + 16); }
                if (ks == 2) { CP16(nbase + 3 * BUFB,  pwL); CP16(nbase + 3 * BUFB + 16, pwL + 16); }
            }
            // pass 1: main term (only needs ahi, bh)
#pragma unroll
            for (int mt = 0; mt < 2; mt++)
#pragma unroll
                for (int nt = 0; nt < 4; nt++)
                    MMA_F32(d[mt][nt][0], d[mt][nt][1], d[mt][nt][2], d[mt][nt][3],
                            ahi[mt][0], ahi[mt][1], ahi[mt][2], ahi[mt][3],
                            bh[nt][0], bh[nt][1]);
            // --- group 2: alo + bl, issued under pass-1 shadow ---
            uint32_t alo[2][4];
#pragma unroll
            for (int mt = 0; mt < 2; mt++) {
                uint32_t rl = sAl + ((a_row + mt * 16) * PITCH + kk * 16 + a_koff) * 2;
                LDSM_X4(alo[mt][0], alo[mt][1], alo[mt][2], alo[mt][3], rl);
            }
            uint32_t bl[4][2];
#pragma unroll
            for (int p = 0; p < 2; p++) {
                uint32_t rbl = sBl + ((b_n + p * 16) * PITCH + kk * 16 + b_koff) * 2;
                uint32_t r0, r1, r2, r3;
                LDSM_X4(r0, r1, r2, r3, rbl);
                bl[2 * p][0] = r0; bl[2 * p][1] = r1;
                bl[2 * p + 1][0] = r2; bl[2 * p + 1][1] = r3;
            }
            // pass 2: ahi x bl
#pragma unroll
            for (int mt = 0; mt < 2; mt++)
#pragma unroll
                for (int nt = 0; nt < 4; nt++)
                    MMA_F16(c16[mt][nt][0], c16[mt][nt][1],
                            ahi[mt][0], ahi[mt][1], ahi[mt][2], ahi[mt][3],
                            bl[nt][0], bl[nt][1]);
            // pass 3: alo x bh
#pragma unroll
            for (int mt = 0; mt < 2; mt++)
#pragma unroll
                for (int nt = 0; nt < 4; nt++)
                    MMA_F16(c16[mt][nt][0], c16[mt][nt][1],
                            alo[mt][0], alo[mt][1], alo[mt][2], alo[mt][3],
                            bh[nt][0], bh[nt][1]);
        }

        if (pf) { CP_COMMIT(); CP_WAIT(0); }
        __syncthreads();
    }

    // ---- epilogue: merge cross, add bias, store Y, BN partials ----
    float* stage = (float*)smp;
#pragma unroll
    for (int mt = 0; mt < 2; mt++)
#pragma unroll
        for (int nt = 0; nt < 4; nt++)
#pragma unroll
            for (int i = 0; i < 4; i++) {
                int row = wm * 32 + mt * 16 + (lane >> 2) + ((i >> 1) << 3);
                int col = wn * 32 + nt * 8 + ((lane & 3) << 1) + (i & 1);
                __half2 hc = *(__half2*)&c16[mt][nt][i >> 1];
                float cross = __half2float((i & 1) ? __high2half(hc) : __low2half(hc));
                stage[row * STAGE_PITCH + col] =
                    d[mt][nt][i] + cross * INV_LOSCALE + sBias[col];
            }
    __syncthreads();

    {
        const int col = t & 127, part = t >> 7;
        float s = 0.f, q = 0.f;
        for (int r = 0; r < 32; r++) {
            int row = part * 32 + r;
            int m = m0 + row;
            float v = stage[row * STAGE_PITCH + col];
            if (m < NN) {
                g_Y[(size_t)m * C + col] = v;
                s += v; q += v * v;
            }
        }
        ((float*)(smp + SM_REDS))[part * 128 + col] = s;
        ((float*)(smp + SM_REDQ))[part * 128 + col] = q;
    }
    __syncthreads();
    if (t < 128) {
        float s = 0.f, q = 0.f;
#pragma unroll
        for (int u = 0; u < 4; u++) {
            s += ((float*)(smp + SM_REDS))[u * 128 + t];
            q += ((float*)(smp + SM_REDQ))[u * 128 + t];
        }
        g_psum[blockIdx.x * C + t] = s;
        g_psq [blockIdx.x * C + t] = q;
    }

    __shared__ int sIsLast;
    __threadfence();
    __syncthreads();
    if (t == 0) {
        int old = atomicAdd(&g_ticket[layer], 1);
        sIsLast = (old == NBM - 1);
    }
    __syncthreads();
    if (sIsLast) {
        const int ch = t & 127, grp = t >> 7;
        float s = 0.f, q = 0.f;
        for (int b = grp; b < NBM; b += 4) {
            s += g_psum[b * C + ch];
            q += g_psq [b * C + ch];
        }
        ((float*)(smp + SM_REDS))[grp * 128 + ch] = s;
        ((float*)(smp + SM_REDQ))[grp * 128 + ch] = q;
        __syncthreads();
        if (t < 128) {
            float S = 0.f, Q = 0.f;
#pragma unroll
            for (int u = 0; u < 4; u++) {
                S += ((float*)(smp + SM_REDS))[u * 128 + t];
                Q += ((float*)(smp + SM_REDQ))[u * 128 + t];
            }
            const float inv_n = 1.f / (float)NN;
            float mu  = S * inv_n;
            float var = Q * inv_n - mu * mu;
            float sc  = gamma[t] * rsqrtf(var + EPSBN);
            g_scale[t] = sc;
            g_shift[t] = beta[t] - mu * sc;
        }
        if (t == 0) g_ticket[layer] = 0;
    }
}

// ---------------- final layer: plain-fp16 MMA, N padded to 64 ----------------
#define F_ABUF  18432
#define F_WBUF  9216
#define F_STAGE (F_ABUF + F_WBUF)        // 27648
#define F_SMEM  (2 * F_STAGE)            // 55296

__global__ void __launch_bounds__(256, 2)
final_mma(const int* __restrict__ idx,
          const float* __restrict__ bl, float* __restrict__ out)
{
    extern __shared__ char smp[];
    const uint32_t sb = smem_u32(smp);
    const int t    = threadIdx.x;
    const int lane = t & 31;
    const int wid  = t >> 5;
    const int wm   = wid >> 1;
    const int wn   = wid & 1;
    const int m0   = blockIdx.x * 128;

    const int arow = t >> 1, aseg = t & 1;
    const int wrow = t >> 2, wq   = t & 3;
    int nbr[7];
    {
        int m = m0 + arow;
        int mm = (m < NN) ? m : 0;
#pragma unroll
        for (int j = 0; j < 7; j++) nbr[j] = idx[mm * 7 + j];
    }
    const __half* wsrc = g_Wlf + (size_t)wrow * 896;
    const uint32_t aDst = (uint32_t)arow * (PITCH * 2) + (uint32_t)aseg * 64;
    const uint32_t wDst = (uint32_t)wrow * (PITCH * 2) + (uint32_t)wq * 32;

    auto issueAll = [&](int c, int s) {
        const int j = c >> 1, h = c & 1;
        const char* aH = (const char*)(g_Xhi + (size_t)nbr[j] * C + h * 64) + aseg * 64;
        const char* wS = (const char*)(wsrc + c * 64) + wq * 32;
        uint32_t base = sb + s * F_STAGE;
#pragma unroll
        for (int q = 0; q < 4; q++) CP16(base + aDst + q * 16, aH + q * 16);
        CP16(base + F_ABUF + wDst,      wS);
        CP16(base + F_ABUF + wDst + 16, wS + 16);
        CP_COMMIT();
    };

    float d[2][4][4];
#pragma unroll
    for (int mt = 0; mt < 2; mt++)
#pragma unroll
        for (int nt = 0; nt < 4; nt++)
#pragma unroll
            for (int i = 0; i < 4; i++) d[mt][nt][i] = 0.f;

    const int a_row  = wm * 32 + (lane & 15);
    const int a_koff = (lane >> 4) * 8;
    const int b_n    = wn * 32 + (lane & 7) + ((lane >> 4) & 1) * 8;
    const int b_koff = ((lane >> 3) & 1) * 8;
    const int kph    = wid & 3;

    issueAll(0, 0);
    CP_WAIT(0);
    __syncthreads();

    for (int c = 0; c < 14; c++) {
        const int s = c & 1;
        const uint32_t sA = sb + s * F_STAGE;
        const uint32_t sW = sA + F_ABUF;

        const bool pf = (c + 1 < 14);
        const char *paH = nullptr, *pwS = nullptr;
        uint32_t nbase = 0;
        if (pf) {
            const int cn = c + 1, j = cn >> 1, h = cn & 1;
            paH = (const char*)(g_Xhi + (size_t)nbr[j] * C + h * 64) + aseg * 64;
            pwS = (const char*)(wsrc + cn * 64) + wq * 32;
            nbase = sb + (s ^ 1) * F_STAGE;
        }

#pragma unroll
        for (int ks = 0; ks < 4; ks++) {
            const int kk = (ks + kph) & 3;
            uint32_t a[2][4];
#pragma unroll
            for (int mt = 0; mt < 2; mt++) {
                uint32_t ra = sA + ((a_row + mt * 16) * PITCH + kk * 16 + a_koff) * 2;
                LDSM_X4(a[mt][0], a[mt][1], a[mt][2], a[mt][3], ra);
            }
            uint32_t bw[4][2];
#pragma unroll
            for (int p = 0; p < 2; p++) {
                uint32_t rb = sW + ((b_n + p * 16) * PITCH + kk * 16 + b_koff) * 2;
                uint32_t r0, r1, r2, r3;
                LDSM_X4(r0, r1, r2, r3, rb);
                bw[2 * p][0] = r0; bw[2 * p][1] = r1;
                bw[2 * p + 1][0] = r2; bw[2 * p + 1][1] = r3;
            }
            if (pf) {
                if (ks == 0) { CP16(nbase + aDst,      paH);      CP16(nbase + aDst + 16, paH + 16); }
                if (ks == 1) { CP16(nbase + aDst + 32, paH + 32); CP16(nbase + aDst + 48, paH + 48); }
                if (ks == 2) { CP16(nbase + F_ABUF + wDst,      pwS);
                               CP16(nbase + F_ABUF + wDst + 16, pwS + 16); }
            }
#pragma unroll
            for (int mt = 0; mt < 2; mt++)
#pragma unroll
                for (int nt = 0; nt < 4; nt++)
                    MMA_F32(d[mt][nt][0], d[mt][nt][1], d[mt][nt][2], d[mt][nt][3],
                            a[mt][0], a[mt][1], a[mt][2], a[mt][3],
                            bw[nt][0], bw[nt][1]);
        }
        if (pf) { CP_COMMIT(); CP_WAIT(0); }
        __syncthreads();
    }

#pragma unroll
    for (int mt = 0; mt < 2; mt++)
#pragma unroll
        for (int nt = 0; nt < 4; nt++)
#pragma unroll
            for (int i = 0; i < 4; i++) {
                int row = wm * 32 + mt * 16 + (lane >> 2) + ((i >> 1) << 3);
                int col = wn * 32 + nt * 8 + ((lane & 3) << 1) + (i & 1);
                int m = m0 + row;
                if (col < NCLS && m < NN)
                    out[(size_t)m * NCLS + col] = d[mt][nt][i] + __ldg(&bl[col]);
            }
}

// ---------------- launch ----------------
extern "C" void kernel_launch(void* const* d_in, const int* in_sizes, int n_in,
                              void* d_out, int out_size)
{
    const float* x   = (const float*)d_in[0];
    const int*   idx = (const int*)  d_in[1];
    const float* W0  = (const float*)d_in[2];
    const float* b0  = (const float*)d_in[3];
    const float* g0  = (const float*)d_in[4];
    const float* be0 = (const float*)d_in[5];
    const float* Wm  = (const float*)d_in[6];
    const float* bm  = (const float*)d_in[7];
    const float* gm  = (const float*)d_in[8];
    const float* bem = (const float*)d_in[9];
    const float* Wl  = (const float*)d_in[10];
    const float* bl  = (const float*)d_in[11];
    float* out = (float*)d_out;

    cudaFuncSetAttribute(gemm_mma, cudaFuncAttributeMaxDynamicSharedMemorySize, GEMM_SMEM);
    cudaFuncSetAttribute(final_mma, cudaFuncAttributeMaxDynamicSharedMemorySize, F_SMEM);

    prep_w<<<dim3(28, 4, NLAY), dim3(32, 32)>>>(Wm);
    prep_wl<<<(64 * 896 + 255) / 256, 256>>>(Wl);
    layer0_kernel<<<NB0, 128>>>(x, idx, W0, b0);
    stats_final<<<1, 1024>>>(NB0, g0, be0);
    convert_kernel<<<(NN * 16 + 511) / 512, 512>>>();

    for (int l = 0; l < NLAY; l++) {
        gemm_mma<<<NBM, 512, GEMM_SMEM>>>(l, idx,
                                          bm + (size_t)l * C,
                                          gm + (size_t)l * C,
                                          bem + (size_t)l * C);
        convert_kernel<<<(NN * 16 + 511) / 512, 512>>>();
    }

    final_mma<<<NBM, 256, F_SMEM>>>(idx, bl, out);
}

// round 16
// speedup vs baseline: 1.0231x; 1.0231x over previous
#include <cuda_runtime.h>
#include <cuda_fp16.h>
#include <cstdint>

// BrainSphereCNN on GB300. Round 16: consolidation. gemm_mma reverted
// byte-for-byte to the R14 best (R13 stagger pipeline); keep R15's faster
// stats_final; layer0 parallelized 2x. Numerics: middle fp16 hi/lo 3-term,
// final plain fp16. rel_err ~2.8e-4.

#define NN    40962
#define C     128
#define NB0   641
#define NBM   321
#define NCLS  36
#define EPSBN 1e-5f
#define NLAY  14
#define LOSCALE 2048.0f
#define INV_LOSCALE (1.0f / 2048.0f)

// ---------------- device scratch ----------------
__device__ float   g_Y[(size_t)NN * C];
__device__ __half  g_Xhi[(size_t)NN * C];
__device__ __half  g_Xlo[(size_t)NN * C];
__device__ __half  g_Whi[(size_t)NLAY * C * 896];  // W^T hi [l][n][k]
__device__ __half  g_Wlo[(size_t)NLAY * C * 896];  // W^T lo * 2048
__device__ __half  g_Wlf[64 * 896];                // final W^T fp16, N padded
__device__ float   g_psum[NB0 * C];
__device__ float   g_psq [NB0 * C];
__device__ float   g_scale[C];
__device__ float   g_shift[C];
__device__ int     g_ticket[NLAY];

// ---------------- PTX helpers ----------------
__device__ __forceinline__ uint32_t smem_u32(const void* p) {
    uint32_t a;
    asm("{ .reg .u64 t; cvta.to.shared.u64 t, %1; cvt.u32.u64 %0, t; }" : "=r"(a) : "l"(p));
    return a;
}

#define LDSM_X4(r0, r1, r2, r3, addr) \
    asm volatile("ldmatrix.sync.aligned.m8n8.x4.shared.b16 {%0,%1,%2,%3}, [%4];" \
                 : "=r"(r0), "=r"(r1), "=r"(r2), "=r"(r3) : "r"(addr))

#define MMA_F32(d0, d1, d2, d3, a0, a1, a2, a3, b0, b1) \
    asm volatile("mma.sync.aligned.m16n8k16.row.col.f32.f16.f16.f32 " \
                 "{%0,%1,%2,%3}, {%4,%5,%6,%7}, {%8,%9}, {%0,%1,%2,%3};" \
                 : "+f"(d0), "+f"(d1), "+f"(d2), "+f"(d3) \
                 : "r"(a0), "r"(a1), "r"(a2), "r"(a3), "r"(b0), "r"(b1))

#define MMA_F16(c0, c1, a0, a1, a2, a3, b0, b1) \
    asm volatile("mma.sync.aligned.m16n8k16.row.col.f16.f16.f16.f16 " \
                 "{%0,%1}, {%2,%3,%4,%5}, {%6,%7}, {%0,%1};" \
                 : "+r"(c0), "+r"(c1) \
                 : "r"(a0), "r"(a1), "r"(a2), "r"(a3), "r"(b0), "r"(b1))

#define CP16(dst, src) \
    asm volatile("cp.async.cg.shared.global [%0], [%1], 16;" :: "r"(dst), "l"(src) : "memory")
#define CP_COMMIT() asm volatile("cp.async.commit_group;" ::: "memory")
#define CP_WAIT(n)  asm volatile("cp.async.wait_group %0;" :: "n"(n) : "memory")

// ---------------- weight prep (middle layers) ----------------
__global__ void prep_w(const float* __restrict__ Wm) {
    __shared__ float tile[32][33];
    const int l = blockIdx.z, k0 = blockIdx.x * 32, n0 = blockIdx.y * 32;
    const int tx = threadIdx.x, ty = threadIdx.y;
    tile[ty][tx] = Wm[((size_t)l * 896 + k0 + ty) * 128 + n0 + tx];
    __syncthreads();
    float w = tile[tx][ty];
    __half hi = __float2half_rn(w);
    __half lo = __float2half_rn((w - __half2float(hi)) * LOSCALE);
    size_t o = ((size_t)l * 128 + n0 + ty) * 896 + (k0 + tx);
    g_Whi[o] = hi;
    g_Wlo[o] = lo;
}

// ---------------- weight prep (final layer) ----------------
__global__ void prep_wl(const float* __restrict__ Wl) {
    int o = blockIdx.x * 256 + threadIdx.x;
    if (o >= 64 * 896) return;
    int n = o / 896, k = o - n * 896;
    float v = (n < NCLS) ? Wl[(size_t)k * NCLS + n] : 0.f;
    g_Wlf[o] = __float2half_rn(v);
}

// ---------------- layer 0: [N,21]@[21,128], 256 thr, 2 row-halves ------------
__global__ __launch_bounds__(256) void layer0_kernel(
    const float* __restrict__ x, const int* __restrict__ idx,
    const float* __restrict__ W0, const float* __restrict__ b0)
{
    __shared__ float sA[64 * 21];
    __shared__ float rS[2][128], rQ[2][128];
    const int t  = threadIdx.x;
    const int ch = t & 127;            // channel
    const int rh = t >> 7;             // row half: 0 -> rows 0..31, 1 -> 32..63
    const int m0 = blockIdx.x * 64;

    for (int e = t; e < 64 * 21; e += 256) {
        int r = e / 21, k = e - r * 21;
        int m = m0 + r;
        float v = 0.f;
        if (m < NN) {
            int j = k / 3, c = k - j * 3;
            v = x[idx[m * 7 + j] * 3 + c];
        }
        sA[e] = v;
    }
    __syncthreads();
    float w[21];
#pragma unroll
    for (int k = 0; k < 21; k++) w[k] = W0[k * C + ch];
    const float bias = b0[ch];
    float s = 0.f, sq = 0.f;
    int r0 = rh * 32;
    int rend = NN - m0; if (rend > 64) rend = 64;
    int r1 = r0 + 32; if (r1 > rend) r1 = rend;
    for (int r = r0; r < r1; r++) {
        float acc = bias;
#pragma unroll
        for (int k = 0; k < 21; k++) acc = fmaf(sA[r * 21 + k], w[k], acc);
        g_Y[(size_t)(m0 + r) * C + ch] = acc;
        s += acc; sq += acc * acc;
    }
    rS[rh][ch] = s; rQ[rh][ch] = sq;
    __syncthreads();
    if (t < 128) {
        g_psum[blockIdx.x * C + t] = rS[0][t] + rS[1][t];
        g_psq [blockIdx.x * C + t] = rQ[0][t] + rQ[1][t];
    }
}

// ---------------- BN stats finalize (layer 0 only), float4 x 32-slice --------
__global__ __launch_bounds__(1024) void stats_final(int nblk, const float* __restrict__ g,
                                                    const float* __restrict__ be)
{
    __shared__ float sS[32][128], sQ[32][128];
    const int t  = threadIdx.x;
    const int cg = t & 31;
    const int sl = t >> 5;
    float4 s = make_float4(0.f, 0.f, 0.f, 0.f);
    float4 q = make_float4(0.f, 0.f, 0.f, 0.f);
    for (int b = sl; b < nblk; b += 32) {
        float4 ps = *(const float4*)&g_psum[b * C + cg * 4];
        float4 pq = *(const float4*)&g_psq [b * C + cg * 4];
        s.x += ps.x; s.y += ps.y; s.z += ps.z; s.w += ps.w;
        q.x += pq.x; q.y += pq.y; q.z += pq.z; q.w += pq.w;
    }
    *(float4*)&sS[sl][cg * 4] = s;
    *(float4*)&sQ[sl][cg * 4] = q;
    __syncthreads();
    if (t < 128) {
        float S = 0.f, Q = 0.f;
#pragma unroll
        for (int u = 0; u < 32; u++) { S += sS[u][t]; Q += sQ[u][t]; }
        const float inv_n = 1.f / (float)NN;
        float mu  = S * inv_n;
        float var = Q * inv_n - mu * mu;
        float sc  = g[t] * rsqrtf(var + EPSBN);
        g_scale[t] = sc;
        g_shift[t] = be[t] - mu * sc;
    }
}

// ---------------- convert: Y -> fp16 hi + scaled lo (8 channels/thread) ------
__global__ __launch_bounds__(512) void convert_kernel() {
    int e = blockIdx.x * 512 + threadIdx.x;
    if (e >= NN * 16) return;
    const int c0 = (e & 15) * 8;
    const float4* src = (const float4*)g_Y + e * 2;
    float4 ya = src[0], yb = src[1];
    float p[8] = { ya.x, ya.y, ya.z, ya.w, yb.x, yb.y, yb.z, yb.w };
    uint32_t hw[4], lw[4];
#pragma unroll
    for (int i = 0; i < 4; i++) {
        float h0 = fmaxf(fmaf(p[2*i],   g_scale[c0 + 2*i],   g_shift[c0 + 2*i]),   0.f);
        float h1 = fmaxf(fmaf(p[2*i+1], g_scale[c0 + 2*i+1], g_shift[c0 + 2*i+1]), 0.f);
        __half a0 = __float2half_rn(h0), a1 = __float2half_rn(h1);
        __half l0 = __float2half_rn((h0 - __half2float(a0)) * LOSCALE);
        __half l1 = __float2half_rn((h1 - __half2float(a1)) * LOSCALE);
        hw[i] = (uint32_t)__half_as_ushort(a0) | ((uint32_t)__half_as_ushort(a1) << 16);
        lw[i] = (uint32_t)__half_as_ushort(l0) | ((uint32_t)__half_as_ushort(l1) << 16);
    }
    ((uint4*)g_Xhi)[e] = make_uint4(hw[0], hw[1], hw[2], hw[3]);
    ((uint4*)g_Xlo)[e] = make_uint4(lw[0], lw[1], lw[2], lw[3]);
}

// ---------------- middle layer GEMM (R13/R14 best, UNCHANGED) ----------------
#define PITCH   72
#define BUFB    18432
#define STAGEB  (4 * BUFB)               // 73728
#define SM_REDS STAGEB
#define SM_REDQ (SM_REDS + 2048)
#define SM_IDX  (2 * STAGEB)             // 147456 : 896 ints
#define SM_BIAS (SM_IDX + 3584)
#define GEMM_SMEM (SM_BIAS + 512)        // 151552
#define STAGE_PITCH 132

__global__ void __launch_bounds__(512, 1)
gemm_mma(int layer, const int* __restrict__ idx,
         const float* __restrict__ bias,
         const float* __restrict__ gamma, const float* __restrict__ beta)
{
    extern __shared__ char smp[];
    const uint32_t sb = smem_u32(smp);
    const int t    = threadIdx.x;
    const int lane = t & 31;
    const int wid  = t >> 5;
    const int wm   = wid >> 2;
    const int wn   = wid & 3;
    const int m0   = blockIdx.x * 128;

    const __half* __restrict__ Whi = g_Whi + (size_t)layer * C * 896;
    const __half* __restrict__ Wlo = g_Wlo + (size_t)layer * C * 896;

    int* sIdx = (int*)(smp + SM_IDX);
    float* sBias = (float*)(smp + SM_BIAS);
    for (int e = t; e < 896; e += 512) {
        int row = e / 7, j = e - row * 7;
        int m = m0 + row;
        sIdx[e] = (m < NN) ? idx[m * 7 + j] : 0;
    }
    if (t < 128) sBias[t] = bias[t];
    __syncthreads();

    const int grow = t >> 2;
    const int gq   = t & 3;
    const uint32_t dstOff = (uint32_t)grow * (PITCH * 2) + (uint32_t)gq * 32;
    const __half* wHrow = Whi + (size_t)grow * 896;
    const __half* wLrow = Wlo + (size_t)grow * 896;

    auto issueAll = [&](int c, int s) {
        const int j = c >> 1, h = c & 1;
        const int nb = sIdx[grow * 7 + j];
        const char* aH = (const char*)(g_Xhi + (size_t)nb * C + h * 64) + gq * 32;
        const char* aL = (const char*)(g_Xlo + (size_t)nb * C + h * 64) + gq * 32;
        const char* wH = (const char*)(wHrow + c * 64) + gq * 32;
        const char* wL = (const char*)(wLrow + c * 64) + gq * 32;
        uint32_t base = sb + s * STAGEB + dstOff;
        CP16(base,                 aH);
        CP16(base + 16,            aH + 16);
        CP16(base + BUFB,          aL);
        CP16(base + BUFB + 16,     aL + 16);
        CP16(base + 2 * BUFB,      wH);
        CP16(base + 2 * BUFB + 16, wH + 16);
        CP16(base + 3 * BUFB,      wL);
        CP16(base + 3 * BUFB + 16, wL + 16);
        CP_COMMIT();
    };

    float    d[2][4][4];
    uint32_t c16[2][4][2];
#pragma unroll
    for (int mt = 0; mt < 2; mt++)
#pragma unroll
        for (int nt = 0; nt < 4; nt++) {
#pragma unroll
            for (int i = 0; i < 4; i++) d[mt][nt][i] = 0.f;
            c16[mt][nt][0] = 0u; c16[mt][nt][1] = 0u;
        }

    const int a_row  = wm * 32 + (lane & 15);
    const int a_koff = (lane >> 4) * 8;
    const int b_n    = wn * 32 + (lane & 7) + ((lane >> 4) & 1) * 8;
    const int b_koff = ((lane >> 3) & 1) * 8;
    const int kph    = wid & 3;

    issueAll(0, 0);
    CP_WAIT(0);
    __syncthreads();

    for (int c = 0; c < 14; c++) {
        const int s = c & 1;
        const uint32_t sAh = sb + s * STAGEB;
        const uint32_t sAl = sAh + BUFB;
        const uint32_t sBh = sAh + 2 * BUFB;
        const uint32_t sBl = sAh + 3 * BUFB;

        const bool pf = (c + 1 < 14);
        const char *paH = nullptr, *paL = nullptr, *pwH = nullptr, *pwL = nullptr;
        uint32_t nbase = 0;
        if (pf) {
            const int cn = c + 1, j = cn >> 1, h = cn & 1;
            const int nb = sIdx[grow * 7 + j];
            paH = (const char*)(g_Xhi + (size_t)nb * C + h * 64) + gq * 32;
            paL = (const char*)(g_Xlo + (size_t)nb * C + h * 64) + gq * 32;
            pwH = (const char*)(wHrow + cn * 64) + gq * 32;
            pwL = (const char*)(wLrow + cn * 64) + gq * 32;
            nbase = sb + (s ^ 1) * STAGEB + dstOff;
        }

#pragma unroll
        for (int ks = 0; ks < 4; ks++) {
            const int kk = (ks + kph) & 3;
            uint32_t ahi[2][4], alo[2][4];
#pragma unroll
            for (int mt = 0; mt < 2; mt++) {
                uint32_t ra = sAh + ((a_row + mt * 16) * PITCH + kk * 16 + a_koff) * 2;
                LDSM_X4(ahi[mt][0], ahi[mt][1], ahi[mt][2], ahi[mt][3], ra);
                uint32_t rl = sAl + ((a_row + mt * 16) * PITCH + kk * 16 + a_koff) * 2;
                LDSM_X4(alo[mt][0], alo[mt][1], alo[mt][2], alo[mt][3], rl);
            }
            uint32_t bh[4][2], bl[4][2];
#pragma unroll
            for (int p = 0; p < 2; p++) {
                uint32_t rb = sBh + ((b_n + p * 16) * PITCH + kk * 16 + b_koff) * 2;
                uint32_t r0, r1, r2, r3;
                LDSM_X4(r0, r1, r2, r3, rb);
                bh[2 * p][0] = r0; bh[2 * p][1] = r1;
                bh[2 * p + 1][0] = r2; bh[2 * p + 1][1] = r3;
                uint32_t rbl = sBl + ((b_n + p * 16) * PITCH + kk * 16 + b_koff) * 2;
                LDSM_X4(r0, r1, r2, r3, rbl);
                bl[2 * p][0] = r0; bl[2 * p][1] = r1;
                bl[2 * p + 1][0] = r2; bl[2 * p + 1][1] = r3;
            }
            if (pf) {
                if (ks == 0) { CP16(nbase,            paH); CP16(nbase + 16,            paH + 16); }
                if (ks == 1) { CP16(nbase + BUFB,     paL); CP16(nbase + BUFB + 16,     paL + 16); }
                if (ks == 2) { CP16(nbase + 2 * BUFB, pwH); CP16(nbase + 2 * BUFB + 16, pwH + 16); }
                if (ks == 3) { CP16(nbase + 3 * BUFB, pwL); CP16(nbase + 3 * BUFB + 16, pwL + 16); }
            }
#pragma unroll
            for (int mt = 0; mt < 2; mt++)
#pragma unroll
                for (int nt = 0; nt < 4; nt++)
                    MMA_F32(d[mt][nt][0], d[mt][nt][1], d[mt][nt][2], d[mt][nt][3],
                            ahi[mt][0], ahi[mt][1], ahi[mt][2], ahi[mt][3],
                            bh[nt][0], bh[nt][1]);
#pragma unroll
            for (int mt = 0; mt < 2; mt++)
#pragma unroll
                for (int nt = 0; nt < 4; nt++)
                    MMA_F16(c16[mt][nt][0], c16[mt][nt][1],
                            ahi[mt][0], ahi[mt][1], ahi[mt][2], ahi[mt][3],
                            bl[nt][0], bl[nt][1]);
#pragma unroll
            for (int mt = 0; mt < 2; mt++)
#pragma unroll
                for (int nt = 0; nt < 4; nt++)
                    MMA_F16(c16[mt][nt][0], c16[mt][nt][1],
                            alo[mt][0], alo[mt][1], alo[mt][2], alo[mt][3],
                            bh[nt][0], bh[nt][1]);
        }

        if (pf) { CP_COMMIT(); CP_WAIT(0); }
        __syncthreads();
    }

    float* stage = (float*)smp;
#pragma unroll
    for (int mt = 0; mt < 2; mt++)
#pragma unroll
        for (int nt = 0; nt < 4; nt++)
#pragma unroll
            for (int i = 0; i < 4; i++) {
                int row = wm * 32 + mt * 16 + (lane >> 2) + ((i >> 1) << 3);
                int col = wn * 32 + nt * 8 + ((lane & 3) << 1) + (i & 1);
                __half2 hc = *(__half2*)&c16[mt][nt][i >> 1];
                float cross = __half2float((i & 1) ? __high2half(hc) : __low2half(hc));
                stage[row * STAGE_PITCH + col] =
                    d[mt][nt][i] + cross * INV_LOSCALE + sBias[col];
            }
    __syncthreads();

    {
        const int col = t & 127, part = t >> 7;
        float s = 0.f, q = 0.f;
        for (int r = 0; r < 32; r++) {
            int row = part * 32 + r;
            int m = m0 + row;
            float v = stage[row * STAGE_PITCH + col];
            if (m < NN) {
                g_Y[(size_t)m * C + col] = v;
                s += v; q += v * v;
            }
        }
        ((float*)(smp + SM_REDS))[part * 128 + col] = s;
        ((float*)(smp + SM_REDQ))[part * 128 + col] = q;
    }
    __syncthreads();
    if (t < 128) {
        float s = 0.f, q = 0.f;
#pragma unroll
        for (int u = 0; u < 4; u++) {
            s += ((float*)(smp + SM_REDS))[u * 128 + t];
            q += ((float*)(smp + SM_REDQ))[u * 128 + t];
        }
        g_psum[blockIdx.x * C + t] = s;
        g_psq [blockIdx.x * C + t] = q;
    }

    __shared__ int sIsLast;
    __threadfence();
    __syncthreads();
    if (t == 0) {
        int old = atomicAdd(&g_ticket[layer], 1);
        sIsLast = (old == NBM - 1);
    }
    __syncthreads();
    if (sIsLast) {
        const int ch = t & 127, grp = t >> 7;
        float s = 0.f, q = 0.f;
        for (int b = grp; b < NBM; b += 4) {
            s += g_psum[b * C + ch];
            q += g_psq [b * C + ch];
        }
        ((float*)(smp + SM_REDS))[grp * 128 + ch] = s;
        ((float*)(smp + SM_REDQ))[grp * 128 + ch] = q;
        __syncthreads();
        if (t < 128) {
            float S = 0.f, Q = 0.f;
#pragma unroll
            for (int u = 0; u < 4; u++) {
                S += ((float*)(smp + SM_REDS))[u * 128 + t];
                Q += ((float*)(smp + SM_REDQ))[u * 128 + t];
            }
            const float inv_n = 1.f / (float)NN;
            float mu  = S * inv_n;
            float var = Q * inv_n - mu * mu;
            float sc  = gamma[t] * rsqrtf(var + EPSBN);
            g_scale[t] = sc;
            g_shift[t] = beta[t] - mu * sc;
        }
        if (t == 0) g_ticket[layer] = 0;
    }
}

// ---------------- final layer: plain-fp16 MMA, N padded to 64 ----------------
#define F_ABUF  18432
#define F_WBUF  9216
#define F_STAGE (F_ABUF + F_WBUF)        // 27648
#define F_SMEM  (2 * F_STAGE)            // 55296

__global__ void __launch_bounds__(256, 2)
final_mma(const int* __restrict__ idx,
          const float* __restrict__ bl, float* __restrict__ out)
{
    extern __shared__ char smp[];
    const uint32_t sb = smem_u32(smp);
    const int t    = threadIdx.x;
    const int lane = t & 31;
    const int wid  = t >> 5;
    const int wm   = wid >> 1;
    const int wn   = wid & 1;
    const int m0   = blockIdx.x * 128;

    const int arow = t >> 1, aseg = t & 1;
    const int wrow = t >> 2, wq   = t & 3;
    int nbr[7];
    {
        int m = m0 + arow;
        int mm = (m < NN) ? m : 0;
#pragma unroll
        for (int j = 0; j < 7; j++) nbr[j] = idx[mm * 7 + j];
    }
    const __half* wsrc = g_Wlf + (size_t)wrow * 896;
    const uint32_t aDst = (uint32_t)arow * (PITCH * 2) + (uint32_t)aseg * 64;
    const uint32_t wDst = (uint32_t)wrow * (PITCH * 2) + (uint32_t)wq * 32;

    auto issueAll = [&](int c, int s) {
        const int j = c >> 1, h = c & 1;
        const char* aH = (const char*)(g_Xhi + (size_t)nbr[j] * C + h * 64) + aseg * 64;
        const char* wS = (const char*)(wsrc + c * 64) + wq * 32;
        uint32_t base = sb + s * F_STAGE;
#pragma unroll
        for (int q = 0; q < 4; q++) CP16(base + aDst + q * 16, aH + q * 16);
        CP16(base + F_ABUF + wDst,      wS);
        CP16(base + F_ABUF + wDst + 16, wS + 16);
        CP_COMMIT();
    };

    float d[2][4][4];
#pragma unroll
    for (int mt = 0; mt < 2; mt++)
#pragma unroll
        for (int nt = 0; nt < 4; nt++)
#pragma unroll
            for (int i = 0; i < 4; i++) d[mt][nt][i] = 0.f;

    const int a_row  = wm * 32 + (lane & 15);
    const int a_koff = (lane >> 4) * 8;
    const int b_n    = wn * 32 + (lane & 7) + ((lane >> 4) & 1) * 8;
    const int b_koff = ((lane >> 3) & 1) * 8;
    const int kph    = wid & 3;

    issueAll(0, 0);
    CP_WAIT(0);
    __syncthreads();

    for (int c = 0; c < 14; c++) {
        const int s = c & 1;
        const uint32_t sA = sb + s * F_STAGE;
        const uint32_t sW = sA + F_ABUF;

        const bool pf = (c + 1 < 14);
        const char *paH = nullptr, *pwS = nullptr;
        uint32_t nbase = 0;
        if (pf) {
            const int cn = c + 1, j = cn >> 1, h = cn & 1;
            paH = (const char*)(g_Xhi + (size_t)nbr[j] * C + h * 64) + aseg * 64;
            pwS = (const char*)(wsrc + cn * 64) + wq * 32;
            nbase = sb + (s ^ 1) * F_STAGE;
        }

#pragma unroll
        for (int ks = 0; ks < 4; ks++) {
            const int kk = (ks + kph) & 3;
            uint32_t a[2][4];
#pragma unroll
            for (int mt = 0; mt < 2; mt++) {
                uint32_t ra = sA + ((a_row + mt * 16) * PITCH + kk * 16 + a_koff) * 2;
                LDSM_X4(a[mt][0], a[mt][1], a[mt][2], a[mt][3], ra);
            }
            uint32_t bw[4][2];
#pragma unroll
            for (int p = 0; p < 2; p++) {
                uint32_t rb = sW + ((b_n + p * 16) * PITCH + kk * 16 + b_koff) * 2;
                uint32_t r0, r1, r2, r3;
                LDSM_X4(r0, r1, r2, r3, rb);
                bw[2 * p][0] = r0; bw[2 * p][1] = r1;
                bw[2 * p + 1][0] = r2; bw[2 * p + 1][1] = r3;
            }
            if (pf) {
                if (ks == 0) { CP16(nbase + aDst,      paH);      CP16(nbase + aDst + 16, paH + 16); }
                if (ks == 1) { CP16(nbase + aDst + 32, paH + 32); CP16(nbase + aDst + 48, paH + 48); }
                if (ks == 2) { CP16(nbase + F_ABUF + wDst,      pwS);
                               CP16(nbase + F_ABUF + wDst + 16, pwS + 16); }
            }
#pragma unroll
            for (int mt = 0; mt < 2; mt++)
#pragma unroll
                for (int nt = 0; nt < 4; nt++)
                    MMA_F32(d[mt][nt][0], d[mt][nt][1], d[mt][nt][2], d[mt][nt][3],
                            a[mt][0], a[mt][1], a[mt][2], a[mt][3],
                            bw[nt][0], bw[nt][1]);
        }
        if (pf) { CP_COMMIT(); CP_WAIT(0); }
        __syncthreads();
    }

#pragma unroll
    for (int mt = 0; mt < 2; mt++)
#pragma unroll
        for (int nt = 0; nt < 4; nt++)
#pragma unroll
            for (int i = 0; i < 4; i++) {
                int row = wm * 32 + mt * 16 + (lane >> 2) + ((i >> 1) << 3);
                int col = wn * 32 + nt * 8 + ((lane & 3) << 1) + (i & 1);
                int m = m0 + row;
                if (col < NCLS && m < NN)
                    out[(size_t)m * NCLS + col] = d[mt][nt][i] + __ldg(&bl[col]);
            }
}

// ---------------- launch ----------------
extern "C" void kernel_launch(void* const* d_in, const int* in_sizes, int n_in,
                              void* d_out, int out_size)
{
    const float* x   = (const float*)d_in[0];
    const int*   idx = (const int*)  d_in[1];
    const float* W0  = (const float*)d_in[2];
    const float* b0  = (const float*)d_in[3];
    const float* g0  = (const float*)d_in[4];
    const float* be0 = (const float*)d_in[5];
    const float* Wm  = (const float*)d_in[6];
    const float* bm  = (const float*)d_in[7];
    const float* gm  = (const float*)d_in[8];
    const float* bem = (const float*)d_in[9];
    const float* Wl  = (const float*)d_in[10];
    const float* bl  = (const float*)d_in[11];
    float* out = (float*)d_out;

    cudaFuncSetAttribute(gemm_mma, cudaFuncAttributeMaxDynamicSharedMemorySize, GEMM_SMEM);
    cudaFuncSetAttribute(final_mma, cudaFuncAttributeMaxDynamicSharedMemorySize, F_SMEM);

    prep_w<<<dim3(28, 4, NLAY), dim3(32, 32)>>>(Wm);
    prep_wl<<<(64 * 896 + 255) / 256, 256>>>(Wl);
    layer0_kernel<<<NB0, 256>>>(x, idx, W0, b0);
    stats_final<<<1, 1024>>>(NB0, g0, be0);
    convert_kernel<<<(NN * 16 + 511) / 512, 512>>>();

    for (int l = 0; l < NLAY; l++) {
        gemm_mma<<<NBM, 512, GEMM_SMEM>>>(l, idx,
                                          bm + (size_t)l * C,
                                          gm + (size_t)l * C,
                                          bem + (size_t)l * C);
        convert_kernel<<<(NN * 16 + 511) / 512, 512>>>();
    }

    final_mma<<<NBM, 256, F_SMEM>>>(idx, bl, out);
}